// round 16
// baseline (speedup 1.0000x reference)
#include <cuda_runtime.h>

#define B   2
#define NQ  900
#define HW  256      // 16*16 argmax domain
#define E   256      // embed dim
#define NH  8        // heads
#define MAXD2 451    // dx^2+dy^2, dx,dy in [-15,15] -> max 450

// Scratch (no allocations allowed -> __device__ globals).
// SELF-CLEANING: k_pair's last block re-zeroes g_cnt/g_p/g_ticket after use,
// so every kernel_launch invocation starts from the zero state (first run:
// static zero-init at module load).
__device__ unsigned char g_cell[B * NQ];    // argmax cell index per (b,q)
__device__ int           g_cnt[B * HW];     // cell histogram per batch
__device__ int           g_p[B * MAXD2];    // pair-count histogram over d2 (EXACT)
__device__ float         g_lut[B * MAXD2];  // bias_mean as function of integer d2
__device__ float         g_mean[B];         // per-batch mean distance
__device__ unsigned int  g_ticket;          // last-block-done counter for k_pair

#if defined(__CUDA_ARCH__) && (__CUDA_ARCH__ >= 900)
#define GRID_DEP_SYNC()  cudaGridDependencySynchronize()
#define GRID_TRIGGER()   cudaTriggerProgrammaticLaunchCompletion()
#else
#define GRID_DEP_SYNC()
#define GRID_TRIGGER()
#endif

// ---------------------------------------------------------------------------
// Kernel 1: per-(b,q) argmax over 256 values (one warp each, 225 blocks x
// 256 threads). Reduction via hardware REDUX: monotonic float->uint map,
// __reduce_max_sync for the value, __reduce_min_sync over matching lanes for
// the FIRST index (matches jnp.argmax). Builds the cell histogram.
// ---------------------------------------------------------------------------
__global__ void k_argmax(const float* __restrict__ rp) {
    int gw   = (blockIdx.x * blockDim.x + threadIdx.x) >> 5;
    int lane = threadIdx.x & 31;
    if (gw >= B * NQ) return;

    const float4* p4 = (const float4*)(rp + (size_t)gw * HW);
    float4 va = p4[lane];        // indices 4*lane .. 4*lane+3
    float4 vb = p4[lane + 32];   // indices 128+4*lane .. +3

    float best = -__int_as_float(0x7f800000); // -inf
    int   bi   = 0;
    float v[8] = {va.x, va.y, va.z, va.w, vb.x, vb.y, vb.z, vb.w};
    #pragma unroll
    for (int k = 0; k < 8; k++) {
        int i = (k < 4 ? 4 * lane + k : 128 + 4 * lane + (k - 4));
        if (v[k] > best) { best = v[k]; bi = i; }   // in-lane ascending -> first max
    }
    // monotonic float -> orderable uint (no NaNs in input)
    unsigned int ub = __float_as_uint(best);
    ub ^= (unsigned int)(((int)ub >> 31)) | 0x80000000u;
    unsigned int m = __reduce_max_sync(0xffffffffu, ub);
    int cand = (ub == m) ? bi : 0x7fffffff;
    int win  = __reduce_min_sync(0xffffffffu, (unsigned int)cand);
    if (lane == 0) {
        g_cell[gw] = (unsigned char)win;
        atomicAdd(&g_cnt[(gw / NQ) * HW + win], 1);
    }
}

// ---------------------------------------------------------------------------
// Kernel 2: pair-count histogram over integer d2. One block per (b, cell k);
// thread l handles pair (k,l). All-integer -> exact & deterministic.
// Last block (ticket): reduces histogram into per-batch mean distance
// (both batch trees fused, fixed order -> bit-identical g_mean), then
// TRIGGERS the dependent launch BEFORE doing the scratch cleanup -- the
// cleanup tail comes off the critical path.
// ---------------------------------------------------------------------------
__global__ void k_pair() {
    __shared__ int    sP[MAXD2];
    __shared__ int    sCnt[HW];
    __shared__ bool   sLast;
    __shared__ double sRed0[256];
    __shared__ double sRed1[256];

    int b = blockIdx.x >> 8;
    int k = blockIdx.x & 255;
    int t = threadIdx.x;

    sP[t] = 0;
    if (t + 256 < MAXD2) sP[t + 256] = 0;

    GRID_DEP_SYNC();                    // wait for k_argmax's g_cnt

    sCnt[t] = g_cnt[b * HW + t];
    __syncthreads();

    int ck = sCnt[k];
    if (ck) {
        int cl = sCnt[t];
        if (cl) {
            int dx = (k & 15) - (t & 15);
            int dy = (k >> 4) - (t >> 4);
            atomicAdd(&sP[dx * dx + dy * dy], ck * cl);
        }
    }
    __syncthreads();

    int v = sP[t];
    if (v) atomicAdd(&g_p[b * MAXD2 + t], v);
    if (t + 256 < MAXD2) {
        v = sP[t + 256];
        if (v) atomicAdd(&g_p[b * MAXD2 + t + 256], v);
    }

    // ---- last-block-done: finalize means, trigger, then clean scratch ----
    __threadfence();
    if (t == 0)
        sLast = (atomicAdd(&g_ticket, 1u) == (unsigned)(gridDim.x - 1));
    __syncthreads();
    if (!sLast) {
        GRID_TRIGGER();                 // this block's work is published
        return;
    }

    {
        float  r0 = sqrtf((float)t);
        double a0 = (double)g_p[t]         * (double)r0;
        double a1 = (double)g_p[MAXD2 + t] * (double)r0;
        if (t + 256 < MAXD2) {
            float r1 = sqrtf((float)(t + 256));
            a0 += (double)g_p[t + 256]         * (double)r1;
            a1 += (double)g_p[MAXD2 + t + 256] * (double)r1;
        }
        sRed0[t] = a0;
        sRed1[t] = a1;
        __syncthreads();
        for (int s = 128; s; s >>= 1) {
            if (t < s) {
                sRed0[t] += sRed0[t + s];
                sRed1[t] += sRed1[t + s];
            }
            __syncthreads();
        }
        if (t == 0) {
            g_mean[0] = (float)(sRed0[0] / 15.0 / ((double)NQ * (double)NQ));
            g_mean[1] = (float)(sRed1[0] / 15.0 / ((double)NQ * (double)NQ));
        }
        __syncthreads();
    }

    // publish g_mean, THEN release the dependent launch, THEN clean up.
    __threadfence();
    GRID_TRIGGER();

    // self-clean for the next run (off the critical path now)
    for (int i = t; i < B * MAXD2; i += 256) g_p[i] = 0;
    g_cnt[t] = 0;
    g_cnt[t + 256] = 0;
    if (t == 0) g_ticket = 0;
}

// ---------------------------------------------------------------------------
// Kernel 3: LUT build, one warp per entry. PDL prologue computes the
// head-averaged weights from inputs only; the grid sync covers only g_mean.
//   LUT[b][d2] = sum_e relu(t*w1[e]+b1[e]) * mean_h(w2[e,h]) + mean_h(b2),
//   t = (sqrt(d2)/15) / (mean[b] + 1e-6)
// Triggers the dependent k_out right after the g_lut store is published.
// ---------------------------------------------------------------------------
__global__ void k_lut(const float* __restrict__ w1, const float* __restrict__ b1,
                      const float* __restrict__ w2, const float* __restrict__ b2) {
    int gwarp = blockIdx.x * (blockDim.x >> 5) + (threadIdx.x >> 5);
    int lane  = threadIdx.x & 31;
    if (gwarp >= B * MAXD2) { GRID_TRIGGER(); return; }

    // prologue (inputs only — overlaps k_pair under PDL)
    float w1r[8], b1r[8], wsr[8];
    #pragma unroll
    for (int k = 0; k < 8; k++) {
        int i = lane + k * 32;
        w1r[k] = w1[i];
        b1r[k] = b1[i];
        const float4* w2r = (const float4*)(w2 + i * NH);
        float4 wa = w2r[0], wb = w2r[1];
        wsr[k] = ((wa.x + wa.y) + (wa.z + wa.w) +
                  (wb.x + wb.y) + (wb.z + wb.w)) * (1.0f / NH);
    }
    float bm = 0.f;
    #pragma unroll
    for (int h = 0; h < NH; h++) bm += b2[h];
    bm *= (1.0f / NH);

    int   bb  = gwarp >= MAXD2 ? 1 : 0;
    int   d2  = gwarp - bb * MAXD2;
    float dst = sqrtf((float)d2) * (1.0f / 15.0f);

    GRID_DEP_SYNC();                    // wait for k_pair's g_mean

    float tt = dst / (g_mean[bb] + 1e-6f);

    float acc = 0.f;
    #pragma unroll
    for (int k = 0; k < 8; k++)
        acc = fmaf(fmaxf(fmaf(tt, w1r[k], b1r[k]), 0.f), wsr[k], acc);
    #pragma unroll
    for (int off = 16; off; off >>= 1)
        acc += __shfl_down_sync(0xffffffffu, acc, off);
    if (lane == 0) g_lut[gwarp] = acc + bm;

    __threadfence();
    GRID_TRIGGER();
}

// ---------------------------------------------------------------------------
// Kernel 4: out = attn + lam * lut[d2(cell_i, cell_j)].
// 4 rows per block (450 blocks x 512 threads), both float4 loads issued
// back-to-back (MLP_p1=2) in the PDL prologue, before the grid sync.
// ---------------------------------------------------------------------------
__global__ void __launch_bounds__(512) k_out(const float* __restrict__ attn,
                                             const float* __restrict__ lam,
                                             float* __restrict__ out) {
    __shared__ float sLut[MAXD2];

    int t    = threadIdx.x;
    int row0 = blockIdx.x * 4;            // rows row0 .. row0+3 (same batch)
    int b    = row0 >= NQ ? 1 : 0;
    int half = t >> 8;                    // 0/1
    int v    = t & 255;                   // vector index within row
    bool act = v < NQ / 4;                // 225 float4 per row

    int rowA = row0 + half;
    int rowB = row0 + 2 + half;

    // prologue: input-only loads, both in flight before any dependency
    float4 aA = make_float4(0.f, 0.f, 0.f, 0.f);
    float4 aB = aA;
    if (act) {
        aA = *((const float4*)(attn + (size_t)rowA * NQ) + v);
        aB = *((const float4*)(attn + (size_t)rowB * NQ) + v);
    }
    float la = __ldg(lam);

    GRID_DEP_SYNC();                      // wait for g_lut / g_cell

    if (t < MAXD2) sLut[t] = g_lut[b * MAXD2 + t];
    int ciA = g_cell[rowA];
    int ciB = g_cell[rowB];
    uchar4 cj4 = make_uchar4(0, 0, 0, 0);
    if (act) cj4 = *(const uchar4*)(g_cell + b * NQ + v * 4);
    __syncthreads();

    if (!act) return;
    int cjx[4], cjy[4];
    unsigned char cc[4] = {cj4.x, cj4.y, cj4.z, cj4.w};
    #pragma unroll
    for (int k = 0; k < 4; k++) { cjx[k] = cc[k] & 15; cjy[k] = cc[k] >> 4; }

    int cixA = ciA & 15, ciyA = ciA >> 4;
    int cixB = ciB & 15, ciyB = ciB >> 4;

    float avA[4] = {aA.x, aA.y, aA.z, aA.w};
    float avB[4] = {aB.x, aB.y, aB.z, aB.w};
    float rA[4], rB[4];
    #pragma unroll
    for (int k = 0; k < 4; k++) {
        int dxA = cixA - cjx[k], dyA = ciyA - cjy[k];
        int dxB = cixB - cjx[k], dyB = ciyB - cjy[k];
        rA[k] = fmaf(la, sLut[dxA * dxA + dyA * dyA], avA[k]);
        rB[k] = fmaf(la, sLut[dxB * dxB + dyB * dyB], avB[k]);
    }
    *((float4*)(out + (size_t)rowA * NQ) + v) = make_float4(rA[0], rA[1], rA[2], rA[3]);
    *((float4*)(out + (size_t)rowB * NQ) + v) = make_float4(rB[0], rB[1], rB[2], rB[3]);
}

// ---------------------------------------------------------------------------
// Launch: 4 kernels chained with Programmatic Dependent Launch.
// ---------------------------------------------------------------------------
static inline void pdl_cfg(cudaLaunchConfig_t* cfg, cudaLaunchAttribute* attr,
                           dim3 grid, dim3 block) {
    attr->id = cudaLaunchAttributeProgrammaticStreamSerialization;
    attr->val.programmaticStreamSerializationAllowed = 1;
    cfg->gridDim = grid;
    cfg->blockDim = block;
    cfg->dynamicSmemBytes = 0;
    cfg->stream = 0;          // legacy default stream (same as <<<>>>)
    cfg->attrs = attr;
    cfg->numAttrs = 1;
}

extern "C" void kernel_launch(void* const* d_in, const int* in_sizes, int n_in,
                              void* d_out, int out_size) {
    const float* attn = (const float*)d_in[0];
    const float* rp   = (const float*)d_in[1];
    const float* lam  = (const float*)d_in[2];
    const float* w1   = (const float*)d_in[3];
    const float* b1   = (const float*)d_in[4];
    const float* w2   = (const float*)d_in[5];
    const float* b2   = (const float*)d_in[6];
    float*       out  = (float*)d_out;

    // primary: 1800 warps, 1 query each = 225 blocks
    k_argmax<<<(B * NQ * 32) / 256, 256>>>(rp);

    cudaLaunchConfig_t cfg;
    cudaLaunchAttribute attr;

    pdl_cfg(&cfg, &attr, dim3(B * HW), dim3(256));
    cudaLaunchKernelEx(&cfg, k_pair);

    pdl_cfg(&cfg, &attr, dim3((B * MAXD2 + 7) / 8), dim3(256));
    cudaLaunchKernelEx(&cfg, k_lut, w1, b1, w2, b2);

    pdl_cfg(&cfg, &attr, dim3(B * NQ / 4), dim3(512));
    cudaLaunchKernelEx(&cfg, k_out, attn, lam, out);
}

// round 17
// speedup vs baseline: 1.0135x; 1.0135x over previous
#include <cuda_runtime.h>

#define B   2
#define NQ  900
#define HW  256      // 16*16 argmax domain
#define E   256      // embed dim
#define NH  8        // heads
#define MAXD2 451    // dx^2+dy^2, dx,dy in [-15,15] -> max 450

// Scratch (no allocations allowed -> __device__ globals).
// SELF-CLEANING: k_pair's last block re-zeroes g_cnt/g_p/g_ticket after use,
// so every kernel_launch invocation starts from the zero state (first run:
// static zero-init at module load).
__device__ unsigned char g_cell[B * NQ];    // argmax cell index per (b,q)
__device__ int           g_cnt[B * HW];     // cell histogram per batch
__device__ int           g_p[B * MAXD2];    // pair-count histogram over d2 (EXACT)
__device__ float         g_lut[B * MAXD2];  // bias_mean as function of integer d2
__device__ float         g_mean[B];         // per-batch mean distance
__device__ unsigned int  g_ticket;          // last-block-done counter for k_pair

#if defined(__CUDA_ARCH__) && (__CUDA_ARCH__ >= 900)
#define GRID_DEP_SYNC()  cudaGridDependencySynchronize()
#define GRID_TRIGGER()   cudaTriggerProgrammaticLaunchCompletion()
#else
#define GRID_DEP_SYNC()
#define GRID_TRIGGER()
#endif

// ---------------------------------------------------------------------------
// Kernel 1: per-(b,q) argmax over 256 values (one warp each, 225 blocks x
// 256 threads). Reduction via hardware REDUX: monotonic float->uint map,
// __reduce_max_sync for the value, __reduce_min_sync over matching lanes for
// the FIRST index (matches jnp.argmax). Builds the cell histogram.
// ---------------------------------------------------------------------------
__global__ void k_argmax(const float* __restrict__ rp) {
    int gw   = (blockIdx.x * blockDim.x + threadIdx.x) >> 5;
    int lane = threadIdx.x & 31;
    if (gw >= B * NQ) return;

    const float4* p4 = (const float4*)(rp + (size_t)gw * HW);
    float4 va = p4[lane];        // indices 4*lane .. 4*lane+3
    float4 vb = p4[lane + 32];   // indices 128+4*lane .. +3

    float best = -__int_as_float(0x7f800000); // -inf
    int   bi   = 0;
    float v[8] = {va.x, va.y, va.z, va.w, vb.x, vb.y, vb.z, vb.w};
    #pragma unroll
    for (int k = 0; k < 8; k++) {
        int i = (k < 4 ? 4 * lane + k : 128 + 4 * lane + (k - 4));
        if (v[k] > best) { best = v[k]; bi = i; }   // in-lane ascending -> first max
    }
    // monotonic float -> orderable uint (no NaNs in input)
    unsigned int ub = __float_as_uint(best);
    ub ^= (unsigned int)(((int)ub >> 31)) | 0x80000000u;
    unsigned int m = __reduce_max_sync(0xffffffffu, ub);
    int cand = (ub == m) ? bi : 0x7fffffff;
    int win  = __reduce_min_sync(0xffffffffu, (unsigned int)cand);
    if (lane == 0) {
        g_cell[gw] = (unsigned char)win;
        atomicAdd(&g_cnt[(gw / NQ) * HW + win], 1);
    }
}

// ---------------------------------------------------------------------------
// Kernel 2: pair-count histogram over integer d2. One block per (b, cell k);
// thread l handles pair (k,l). All-integer -> exact & deterministic.
// Last block (ticket): reduces histogram into per-batch mean distance
// (both batch trees fused, fixed order -> bit-identical g_mean), then
// TRIGGERS the dependent launch BEFORE the scratch cleanup.
// ---------------------------------------------------------------------------
__global__ void k_pair() {
    __shared__ int    sP[MAXD2];
    __shared__ int    sCnt[HW];
    __shared__ bool   sLast;
    __shared__ double sRed0[256];
    __shared__ double sRed1[256];

    int b = blockIdx.x >> 8;
    int k = blockIdx.x & 255;
    int t = threadIdx.x;

    sP[t] = 0;
    if (t + 256 < MAXD2) sP[t + 256] = 0;

    GRID_DEP_SYNC();                    // wait for k_argmax's g_cnt

    sCnt[t] = g_cnt[b * HW + t];
    __syncthreads();

    int ck = sCnt[k];
    if (ck) {
        int cl = sCnt[t];
        if (cl) {
            int dx = (k & 15) - (t & 15);
            int dy = (k >> 4) - (t >> 4);
            atomicAdd(&sP[dx * dx + dy * dy], ck * cl);
        }
    }
    __syncthreads();

    int v = sP[t];
    if (v) atomicAdd(&g_p[b * MAXD2 + t], v);
    if (t + 256 < MAXD2) {
        v = sP[t + 256];
        if (v) atomicAdd(&g_p[b * MAXD2 + t + 256], v);
    }

    // ---- last-block-done: finalize means, trigger, then clean scratch ----
    __threadfence();
    if (t == 0)
        sLast = (atomicAdd(&g_ticket, 1u) == (unsigned)(gridDim.x - 1));
    __syncthreads();
    if (!sLast) {
        GRID_TRIGGER();                 // this block's work is published
        return;
    }

    {
        float  r0 = sqrtf((float)t);
        double a0 = (double)g_p[t]         * (double)r0;
        double a1 = (double)g_p[MAXD2 + t] * (double)r0;
        if (t + 256 < MAXD2) {
            float r1 = sqrtf((float)(t + 256));
            a0 += (double)g_p[t + 256]         * (double)r1;
            a1 += (double)g_p[MAXD2 + t + 256] * (double)r1;
        }
        sRed0[t] = a0;
        sRed1[t] = a1;
        __syncthreads();
        for (int s = 128; s; s >>= 1) {
            if (t < s) {
                sRed0[t] += sRed0[t + s];
                sRed1[t] += sRed1[t + s];
            }
            __syncthreads();
        }
        if (t == 0) {
            g_mean[0] = (float)(sRed0[0] / 15.0 / ((double)NQ * (double)NQ));
            g_mean[1] = (float)(sRed1[0] / 15.0 / ((double)NQ * (double)NQ));
        }
        __syncthreads();
    }

    // publish g_mean, THEN release the dependent launch, THEN clean up.
    __threadfence();
    GRID_TRIGGER();

    // self-clean for the next run (off the critical path)
    for (int i = t; i < B * MAXD2; i += 256) g_p[i] = 0;
    g_cnt[t] = 0;
    g_cnt[t + 256] = 0;
    if (t == 0) g_ticket = 0;
}

// ---------------------------------------------------------------------------
// Kernel 3: LUT build, one warp per entry. PDL prologue computes the
// head-averaged weights from inputs only; the grid sync covers only g_mean.
//   LUT[b][d2] = sum_e relu(t*w1[e]+b1[e]) * mean_h(w2[e,h]) + mean_h(b2),
//   t = (sqrt(d2)/15) / (mean[b] + 1e-6)
// ---------------------------------------------------------------------------
__global__ void k_lut(const float* __restrict__ w1, const float* __restrict__ b1,
                      const float* __restrict__ w2, const float* __restrict__ b2) {
    int gwarp = blockIdx.x * (blockDim.x >> 5) + (threadIdx.x >> 5);
    int lane  = threadIdx.x & 31;
    if (gwarp >= B * MAXD2) return;

    // prologue (inputs only — overlaps k_pair under PDL)
    float w1r[8], b1r[8], wsr[8];
    #pragma unroll
    for (int k = 0; k < 8; k++) {
        int i = lane + k * 32;
        w1r[k] = w1[i];
        b1r[k] = b1[i];
        const float4* w2r = (const float4*)(w2 + i * NH);
        float4 wa = w2r[0], wb = w2r[1];
        wsr[k] = ((wa.x + wa.y) + (wa.z + wa.w) +
                  (wb.x + wb.y) + (wb.z + wb.w)) * (1.0f / NH);
    }
    float bm = 0.f;
    #pragma unroll
    for (int h = 0; h < NH; h++) bm += b2[h];
    bm *= (1.0f / NH);

    int   bb  = gwarp >= MAXD2 ? 1 : 0;
    int   d2  = gwarp - bb * MAXD2;
    float dst = sqrtf((float)d2) * (1.0f / 15.0f);

    GRID_DEP_SYNC();                    // wait for k_pair's g_mean

    float tt = dst / (g_mean[bb] + 1e-6f);

    float acc = 0.f;
    #pragma unroll
    for (int k = 0; k < 8; k++)
        acc = fmaf(fmaxf(fmaf(tt, w1r[k], b1r[k]), 0.f), wsr[k], acc);
    #pragma unroll
    for (int off = 16; off; off >>= 1)
        acc += __shfl_down_sync(0xffffffffu, acc, off);
    if (lane == 0) g_lut[gwarp] = acc + bm;
}

// ---------------------------------------------------------------------------
// Kernel 4: out = attn + lam * lut[d2(cell_i, cell_j)].
// 4 rows per block (450 blocks x 512 threads), both float4 loads issued
// back-to-back (MLP_p1=2) in the PDL prologue, before the grid sync.
// BARRIER-FREE: no shared-memory LUT staging / __syncthreads — LUT entries
// are read with direct __ldg from the 1.8 KB g_lut region (L1-resident after
// first touch), so each warp proceeds as soon as ITS OWN loads land instead
// of waiting for the block's slowest staging load.
// ---------------------------------------------------------------------------
__global__ void __launch_bounds__(512) k_out(const float* __restrict__ attn,
                                             const float* __restrict__ lam,
                                             float* __restrict__ out) {
    int t    = threadIdx.x;
    int row0 = blockIdx.x * 4;            // rows row0 .. row0+3 (same batch)
    int b    = row0 >= NQ ? 1 : 0;
    int half = t >> 8;                    // 0/1
    int v    = t & 255;                   // vector index within row
    bool act = v < NQ / 4;                // 225 float4 per row

    int rowA = row0 + half;
    int rowB = row0 + 2 + half;

    // prologue: input-only loads, both in flight before any dependency
    float4 aA = make_float4(0.f, 0.f, 0.f, 0.f);
    float4 aB = aA;
    if (act) {
        aA = *((const float4*)(attn + (size_t)rowA * NQ) + v);
        aB = *((const float4*)(attn + (size_t)rowB * NQ) + v);
    }
    float la = __ldg(lam);

    GRID_DEP_SYNC();                      // wait for g_lut / g_cell

    if (!act) return;                     // no barrier -> inactive warps exit

    const float* lutb = g_lut + b * MAXD2;
    int ciA = g_cell[rowA];
    int ciB = g_cell[rowB];
    uchar4 cj4 = *(const uchar4*)(g_cell + b * NQ + v * 4);

    int cjx[4], cjy[4];
    unsigned char cc[4] = {cj4.x, cj4.y, cj4.z, cj4.w};
    #pragma unroll
    for (int k = 0; k < 4; k++) { cjx[k] = cc[k] & 15; cjy[k] = cc[k] >> 4; }

    int cixA = ciA & 15, ciyA = ciA >> 4;
    int cixB = ciB & 15, ciyB = ciB >> 4;

    float avA[4] = {aA.x, aA.y, aA.z, aA.w};
    float avB[4] = {aB.x, aB.y, aB.z, aB.w};
    float rA[4], rB[4];
    #pragma unroll
    for (int k = 0; k < 4; k++) {
        int dxA = cixA - cjx[k], dyA = ciyA - cjy[k];
        int dxB = cixB - cjx[k], dyB = ciyB - cjy[k];
        rA[k] = fmaf(la, __ldg(lutb + dxA * dxA + dyA * dyA), avA[k]);
        rB[k] = fmaf(la, __ldg(lutb + dxB * dxB + dyB * dyB), avB[k]);
    }
    *((float4*)(out + (size_t)rowA * NQ) + v) = make_float4(rA[0], rA[1], rA[2], rA[3]);
    *((float4*)(out + (size_t)rowB * NQ) + v) = make_float4(rB[0], rB[1], rB[2], rB[3]);
}

// ---------------------------------------------------------------------------
// Launch: 4 kernels chained with Programmatic Dependent Launch.
// ---------------------------------------------------------------------------
static inline void pdl_cfg(cudaLaunchConfig_t* cfg, cudaLaunchAttribute* attr,
                           dim3 grid, dim3 block) {
    attr->id = cudaLaunchAttributeProgrammaticStreamSerialization;
    attr->val.programmaticStreamSerializationAllowed = 1;
    cfg->gridDim = grid;
    cfg->blockDim = block;
    cfg->dynamicSmemBytes = 0;
    cfg->stream = 0;          // legacy default stream (same as <<<>>>)
    cfg->attrs = attr;
    cfg->numAttrs = 1;
}

extern "C" void kernel_launch(void* const* d_in, const int* in_sizes, int n_in,
                              void* d_out, int out_size) {
    const float* attn = (const float*)d_in[0];
    const float* rp   = (const float*)d_in[1];
    const float* lam  = (const float*)d_in[2];
    const float* w1   = (const float*)d_in[3];
    const float* b1   = (const float*)d_in[4];
    const float* w2   = (const float*)d_in[5];
    const float* b2   = (const float*)d_in[6];
    float*       out  = (float*)d_out;

    // primary: 1800 warps, 1 query each = 225 blocks
    k_argmax<<<(B * NQ * 32) / 256, 256>>>(rp);

    cudaLaunchConfig_t cfg;
    cudaLaunchAttribute attr;

    pdl_cfg(&cfg, &attr, dim3(B * HW), dim3(256));
    cudaLaunchKernelEx(&cfg, k_pair);

    pdl_cfg(&cfg, &attr, dim3((B * MAXD2 + 7) / 8), dim3(256));
    cudaLaunchKernelEx(&cfg, k_lut, w1, b1, w2, b2);

    pdl_cfg(&cfg, &attr, dim3(B * NQ / 4), dim3(512));
    cudaLaunchKernelEx(&cfg, k_out, attn, lam, out);
}